// round 14
// baseline (speedup 1.0000x reference)
#include <cuda_runtime.h>
#include <cuda_fp16.h>

// ---------------- geometry ----------------
#define NPTS   16384
#define FS     72       // feats/h1/out_pre K-stride (64+8 halves)
#define XS     136      // xn/x3 stride (128+8 halves)
#define XFS    1032     // xfs per-point stride (1024+8 halves)

// ---- pre-packed fp16 A-fragment store (uint4 = af[4] per lane) ----
#define OFF_W0    0        // M=128 K=64   : 8*4*32  = 1024
#define OFF_W1    1024     // M=64  K=128  : 4*8*32  = 1024
#define OFF_W2N   2048     // M=64  K=128  (negated)
#define OFF_W3    3072     // M=64  K=128
#define OFF_PW2   4096     // M=64  K=64   : 4*4*32  = 512
#define OFF_WOUT  4608     // M=128 K=64   : 8*4*32  = 1024
#define FRAG_TOTAL 5632

// ---- half-fragment store (uint2 per lane; other half is zeros) ----
#define OFF2_CW1  0        // 64 chunks (M=8 rows 8-15 zero):  64*32 = 2048
#define OFF2_PW1  2048     // 4 chunks  (K=8, k 8-15 zero):    4*32  = 128
#define OFF2_CW2  2176     // 8 chunks  (K=8):                 8*32  = 256
#define FRAG2_TOTAL 2432

__device__ uint4 g_wfrag[FRAG_TOTAL];
__device__ uint2 g_wfrag2[FRAG2_TOTAL];

struct Smem {
    union {
        __half feats[128][FS];     // 18432 B  (stage 0 -> 1)   [4-bit XOR swizzle]
        __half h1[128][FS];        //          (stage 2 -> 3)   [4-bit XOR swizzle]
    } A;
    __half xfs[8][XFS];            // 16512 B  (dedicated: no sync needed st3->st4/5)
    __half xn[128][XS];            // 34816 B
    __half x3[64][XS];             // 17408 B  [pt-block swizzled by K3(row)]
    __half ppfs[128][8];           // 2048 B
    float  x1[64][8];              // 2048 B
    float  part[8][8][8];          // 2048 B   [warp][j][pt]
    __half hbufh[8][8];            // 128 B    [pt][j]
    __half w16[8][8][24];          // 3072 B   [pt][gg][k]  (gg-stride 48B: bank-safe)
    __half xk0[8][136];            // 2176 B   [pt][P16 pos] k=0 columns of xn
    __half out_pre[8][FS];         // 1152 B   [pt][P16(m)]
};

__device__ __forceinline__ int P16(int i) {
    return 4 * ((i >> 1) & 3) + 2 * (i >> 3) + (i & 1);
}
__device__ __forceinline__ int K3(int r) { return ((r & 7) + (r >> 3)) & 7; }

__device__ __forceinline__ unsigned pack2(float lo, float hi) {
    __half2 h = __floats2half2_rn(lo, hi);
    return *reinterpret_cast<unsigned*>(&h);
}

__device__ __forceinline__ void mma_16816_u4(float* c, uint4 a, const unsigned* b) {
    asm volatile(
        "mma.sync.aligned.m16n8k16.row.col.f32.f16.f16.f32 "
        "{%0,%1,%2,%3}, {%4,%5,%6,%7}, {%8,%9}, {%0,%1,%2,%3};\n"
        : "+f"(c[0]), "+f"(c[1]), "+f"(c[2]), "+f"(c[3])
        : "r"(a.x), "r"(a.y), "r"(a.z), "r"(a.w), "r"(b[0]), "r"(b[1]));
}
__device__ __forceinline__ uint4 ldfrag(int seg, int KC, int m, int ch, int lane) {
    return __ldg(&g_wfrag[seg + (m * KC + ch) * 32 + lane]);
}
// plain B-fragment from a P16-layout smem tile: one 8B load
__device__ __forceinline__ void bfrag16(unsigned bf[2], const __half* T, int S,
                                        int col, int k0, int tig) {
    uint2 v = *reinterpret_cast<const uint2*>(T + col * S + k0 + 4 * tig);
    bf[0] = v.x; bf[1] = v.y;
}
// swizzled B-fragment from region A (FS stride, 4-bit 8B-unit XOR swizzle)
__device__ __forceinline__ void bfragA(unsigned bf[2], const __half* T,
                                       int col, int ch, int tig) {
    int off = col * FS + (((ch * 4 + tig) ^ ((col >> 2) & 15)) << 2);
    uint2 v = *reinterpret_cast<const uint2*>(T + off);
    bf[0] = v.x; bf[1] = v.y;
}
__device__ __forceinline__ uint2 epi_merge(float v0, float v1, float v2, float v3,
                                           int gpar) {
    unsigned ve = pack2(v0, v2);
    unsigned vo = pack2(v1, v3);
    unsigned x  = gpar ? ve : vo;
    unsigned y  = __shfl_xor_sync(0xffffffffu, x, 4);
    unsigned ae = gpar ? y : ve;
    unsigned ao = gpar ? vo : y;
    __half2 he = *reinterpret_cast<__half2*>(&ae);
    __half2 ho = *reinterpret_cast<__half2*>(&ao);
    __half2 lo = __lows2half2(he, ho);
    __half2 hi = __highs2half2(he, ho);
    uint2 st;
    st.x = *reinterpret_cast<unsigned*>(&lo);
    st.y = *reinterpret_cast<unsigned*>(&hi);
    return st;
}
__device__ __forceinline__ float dot_h8(uint4 a, uint4 b) {
    const __half2* A = reinterpret_cast<const __half2*>(&a);
    const __half2* B = reinterpret_cast<const __half2*>(&b);
    float s = 0.f;
    #pragma unroll
    for (int i = 0; i < 4; i++) {
        float2 x = __half22float2(A[i]);
        float2 y = __half22float2(B[i]);
        s += x.x * y.x + x.y * y.y;
    }
    return s;
}

// ============== prep kernel: pack fp32 weights -> fp16 fragments ==============
__global__ void pack_weights_kernel(const float* __restrict__ w0,
                                    const float* __restrict__ w1,
                                    const float* __restrict__ w2,
                                    const float* __restrict__ w3,
                                    const float* __restrict__ pw1,
                                    const float* __restrict__ pw2,
                                    const float* __restrict__ cw1,
                                    const float* __restrict__ cw2,
                                    const float* __restrict__ wout)
{
    int idx = blockIdx.x * blockDim.x + threadIdx.x;
    if (idx >= FRAG_TOTAL + FRAG2_TOTAL) return;

    if (idx < FRAG_TOTAL) {
        const float* W; int Mr, Kr, KC; float sgn = 1.f; int seg;
        if      (idx < OFF_W1)   { seg = OFF_W0;   W = w0;   Mr = 128; Kr = 64;  KC = 4; }
        else if (idx < OFF_W2N)  { seg = OFF_W1;   W = w1;   Mr = 64;  Kr = 128; KC = 8; }
        else if (idx < OFF_W3)   { seg = OFF_W2N;  W = w2;   Mr = 64;  Kr = 128; KC = 8; sgn = -1.f; }
        else if (idx < OFF_PW2)  { seg = OFF_W3;   W = w3;   Mr = 64;  Kr = 128; KC = 8; }
        else if (idx < OFF_WOUT) { seg = OFF_PW2;  W = pw2;  Mr = 64;  Kr = 64;  KC = 4; }
        else                     { seg = OFF_WOUT; W = wout; Mr = 128; Kr = 64;  KC = 4; }

        int li = idx - seg;
        int lane = li & 31;
        int chunk = li >> 5;
        int ch = chunk % KC;
        int m  = chunk / KC;
        int g = lane >> 2, tig = lane & 3;
        int r0 = m * 16 + g;
        int kc = ch * 16 + 2 * tig;
        auto f = [&](int r, int c) -> float {
            return (r < Mr && c < Kr) ? sgn * W[r * Kr + c] : 0.f;
        };
        uint4 v;
        v.x = pack2(f(r0, kc),         f(r0, kc + 1));
        v.y = pack2(f(r0 + 8, kc),     f(r0 + 8, kc + 1));
        v.z = pack2(f(r0, kc + 8),     f(r0, kc + 9));
        v.w = pack2(f(r0 + 8, kc + 8), f(r0 + 8, kc + 9));
        g_wfrag[idx] = v;
    } else {
        int i2 = idx - FRAG_TOTAL;
        int lane = i2 & 31;
        int chunk = i2 >> 5;
        int g = lane >> 2, tig = lane & 3;
        uint2 u;
        if (i2 < OFF2_PW1) {
            // cw1: M=8, K=1024; chunk = ch. u = {rows g k pair, rows g k+8 pair}
            int kc = chunk * 16 + 2 * tig;
            u.x = pack2(cw1[g * 1024 + kc],     cw1[g * 1024 + kc + 1]);
            u.y = pack2(cw1[g * 1024 + kc + 8], cw1[g * 1024 + kc + 9]);
        } else if (i2 < OFF2_CW2) {
            // pw1: M=64, K=8; chunk-OFF2 = m. u = {row r0 pair, row r0+8 pair}, k<8
            int m = (i2 - OFF2_PW1) >> 5;
            int r0 = m * 16 + g;
            int kc = 2 * tig;
            u.x = pack2(pw1[r0 * 8 + kc],       pw1[r0 * 8 + kc + 1]);
            u.y = pack2(pw1[(r0 + 8) * 8 + kc], pw1[(r0 + 8) * 8 + kc + 1]);
        } else {
            // cw2: M=128, K=8; chunk-OFF2 = m (gg)
            int m = (i2 - OFF2_CW2) >> 5;
            int r0 = m * 16 + g;
            int kc = 2 * tig;
            u.x = pack2(cw2[r0 * 8 + kc],       cw2[r0 * 8 + kc + 1]);
            u.y = pack2(cw2[(r0 + 8) * 8 + kc], cw2[(r0 + 8) * 8 + kc + 1]);
        }
        g_wfrag2[i2] = u;
    }
}

// ================================ main kernel ================================
__global__ __launch_bounds__(256, 2)
void pt_fused_kernel(const float* __restrict__ feats, const float* __restrict__ ppfs,
                     const float* __restrict__ b0, const float* __restrict__ b1,
                     const float* __restrict__ b2, const float* __restrict__ b3,
                     const float* __restrict__ cb2, const float* __restrict__ bout,
                     float* __restrict__ out)
{
    extern __shared__ char smraw[];
    Smem& sm = *reinterpret_cast<Smem*>(smraw);

    const int tid  = threadIdx.x;
    const int warp = tid >> 5;
    const int lane = tid & 31;
    const int g    = lane >> 2;
    const int tig  = lane & 3;
    const int b    = blockIdx.y;
    const int n0   = blockIdx.x * 8;

    __half* const Abase = &sm.A.feats[0][0];

    // ============ Stage 0: load feats (P16 quads, 4-bit swizzle) + ppfs ============
    {
        #pragma unroll
        for (int qi = 0; qi < 2; qi++) {
            int q   = warp * 2 + qi;
            int grp = q >> 2;
            int a   = 2 * (q & 3);
            int cb  = grp * 16 + a;
            const float4* pA = reinterpret_cast<const float4*>(
                feats + ((size_t)(b * 64 + cb) * NPTS + n0) * 16);
            const float4* pB = reinterpret_cast<const float4*>(
                feats + ((size_t)(b * 64 + cb + 1) * NPTS + n0) * 16);
            const float4* pC = reinterpret_cast<const float4*>(
                feats + ((size_t)(b * 64 + cb + 8) * NPTS + n0) * 16);
            const float4* pD = reinterpret_cast<const float4*>(
                feats + ((size_t)(b * 64 + cb + 9) * NPTS + n0) * 16);
            float4 vA = __ldg(&pA[lane]);
            float4 vB = __ldg(&pB[lane]);
            float4 vC = __ldg(&pC[lane]);
            float4 vD = __ldg(&pD[lane]);
            int u    = grp * 4 + (a >> 1);
            int xr   = (u ^ (lane & 15)) << 2;
            int colb = lane * 4;
            float fA[4] = {vA.x, vA.y, vA.z, vA.w};
            float fB[4] = {vB.x, vB.y, vB.z, vB.w};
            float fC[4] = {vC.x, vC.y, vC.z, vC.w};
            float fD[4] = {vD.x, vD.y, vD.z, vD.w};
            #pragma unroll
            for (int j = 0; j < 4; j++) {
                uint2 st;
                st.x = pack2(fA[j], fB[j]);
                st.y = pack2(fC[j], fD[j]);
                *reinterpret_cast<uint2*>(Abase + (colb + j) * FS + xr) = st;
            }
        }
        if (warp < 4) {
            int c0 = 2 * warp;
            const float4* p0 = reinterpret_cast<const float4*>(
                ppfs + ((size_t)(b * 8 + c0) * NPTS + n0) * 16);
            const float4* p1 = reinterpret_cast<const float4*>(
                ppfs + ((size_t)(b * 8 + c0 + 1) * NPTS + n0) * 16);
            float4 v0 = __ldg(&p0[lane]);
            float4 v1 = __ldg(&p1[lane]);
            int colb = lane * 4;
            float f0[4] = {v0.x, v0.y, v0.z, v0.w};
            float f1[4] = {v1.x, v1.y, v1.z, v1.w};
            #pragma unroll
            for (int j = 0; j < 4; j++)
                *reinterpret_cast<__half2*>(&sm.ppfs[colb + j][c0]) =
                    __floats2half2_rn(f0[j], f1[j]);
        }
    }
    __syncthreads();

    // ==== Stage 1: xn = relu(w0 @ feats + b0). Warp: 2 m-tiles x 64 cols ====
    {
        const int mt0 = 2 * (warp & 3);
        const int nb  = (warp >> 2) * 64;
        float acc[2][8][4];
        #pragma unroll
        for (int q = 0; q < 2; q++)
            #pragma unroll
            for (int nt = 0; nt < 8; nt++)
                acc[q][nt][0] = acc[q][nt][1] = acc[q][nt][2] = acc[q][nt][3] = 0.f;
        #pragma unroll
        for (int ch = 0; ch < 4; ch++) {
            uint4 afA = ldfrag(OFF_W0, 4, mt0,     ch, lane);
            uint4 afB = ldfrag(OFF_W0, 4, mt0 + 1, ch, lane);
            #pragma unroll
            for (int nt = 0; nt < 8; nt++) {
                unsigned bf[2];
                bfragA(bf, Abase, nb + nt * 8 + g, ch, tig);
                mma_16816_u4(acc[0][nt], afA, bf);
                mma_16816_u4(acc[1][nt], afB, bf);
            }
        }
        #pragma unroll
        for (int q = 0; q < 2; q++) {
            int mb = (mt0 + q) * 16;
            float bi0 = __ldg(&b0[mb + g]), bi1 = __ldg(&b0[mb + g + 8]);
            int pbase = mb + 4 * (g >> 1);
            #pragma unroll
            for (int nt = 0; nt < 8; nt++) {
                float* c = acc[q][nt];
                uint2 st = epi_merge(fmaxf(c[0] + bi0, 0.f), fmaxf(c[1] + bi0, 0.f),
                                     fmaxf(c[2] + bi1, 0.f), fmaxf(c[3] + bi1, 0.f),
                                     g & 1);
                int col = nb + nt * 8 + 2 * tig + (g & 1);
                *reinterpret_cast<uint2*>(&sm.xn[col][pbase]) = st;
                if ((col & 15) == 0)
                    *reinterpret_cast<uint2*>(&sm.xk0[col >> 4][pbase]) = st;
            }
        }
    }
    __syncthreads();

    // ===== Stage 2: warps 0-3: x1 = w1 @ xk0 + b1 ; warps 4-7: h1 = relu(pw1 @ ppfs) =====
    if (warp < 4) {
        const int mb = warp * 16;
        float bi0 = __ldg(&b1[mb + g]), bi1 = __ldg(&b1[mb + g + 8]);
        float acc[4] = {bi0, bi0, bi1, bi1};
        #pragma unroll
        for (int ch = 0; ch < 8; ch++) {
            uint4 af = ldfrag(OFF_W1, 8, warp, ch, lane);
            unsigned bf[2];
            bfrag16(bf, &sm.xk0[0][0], 136, g, ch * 16, tig);
            mma_16816_u4(acc, af, bf);
        }
        sm.x1[mb + g][2 * tig]         = acc[0];
        sm.x1[mb + g][2 * tig + 1]     = acc[1];
        sm.x1[mb + g + 8][2 * tig]     = acc[2];
        sm.x1[mb + g + 8][2 * tig + 1] = acc[3];
    } else {
        const int mb = (warp - 4) * 16;
        uint2 u = __ldg(&g_wfrag2[OFF2_PW1 + (warp - 4) * 32 + lane]);
        uint4 af; af.x = u.x; af.y = u.y; af.z = 0u; af.w = 0u;
        int ub = (mb >> 2) + (g >> 1);
        #pragma unroll
        for (int nt = 0; nt < 16; nt++) {
            unsigned bf[2];
            bf[0] = *reinterpret_cast<const unsigned*>(&sm.ppfs[nt * 8 + g][2 * tig]);
            bf[1] = 0u;
            float c[4] = {0.f, 0.f, 0.f, 0.f};
            mma_16816_u4(c, af, bf);
            uint2 st = epi_merge(fmaxf(c[0], 0.f), fmaxf(c[1], 0.f),
                                 fmaxf(c[2], 0.f), fmaxf(c[3], 0.f), g & 1);
            int col = nt * 8 + 2 * tig + (g & 1);
            int off = col * FS + ((ub ^ ((col >> 2) & 15)) << 2);
            *reinterpret_cast<uint2*>(Abase + off) = st;
        }
    }
    __syncthreads();

    // ==== Stage 3 + 4 + 5 fused (no barrier): ptf then x3/xfs ====
    const int mt0 = 2 * (warp & 1);
    const int nb3 = (warp >> 1) * 32;
    float ptfa[2][4][4];
    {
        #pragma unroll
        for (int q = 0; q < 2; q++)
            #pragma unroll
            for (int nt = 0; nt < 4; nt++)
                ptfa[q][nt][0] = ptfa[q][nt][1] = ptfa[q][nt][2] = ptfa[q][nt][3] = 0.f;
        #pragma unroll
        for (int ch = 0; ch < 4; ch++) {
            uint4 afA = ldfrag(OFF_PW2, 4, mt0,     ch, lane);
            uint4 afB = ldfrag(OFF_PW2, 4, mt0 + 1, ch, lane);
            #pragma unroll
            for (int nt = 0; nt < 4; nt++) {
                unsigned bf[2];
                bfragA(bf, Abase, nb3 + nt * 8 + g, ch, tig);
                mma_16816_u4(ptfa[0][nt], afA, bf);
                mma_16816_u4(ptfa[1][nt], afB, bf);
            }
        }
    }
    // (no __syncthreads: xfs is a dedicated buffer; h1 only read above by this warp)
    {
        float c3[2][4][4], c2[2][4][4];
        #pragma unroll
        for (int q = 0; q < 2; q++) {
            int mb = (mt0 + q) * 16;
            float bi30 = __ldg(&b3[mb + g]), bi31 = __ldg(&b3[mb + g + 8]);
            float bi20 = __ldg(&b2[mb + g]), bi21 = __ldg(&b2[mb + g + 8]);
            #pragma unroll
            for (int nt = 0; nt < 4; nt++) {
                int pt = (nb3 >> 4) + (nt >> 1);
                float x1lo = sm.x1[mb + g][pt], x1hi = sm.x1[mb + g + 8][pt];
                c3[q][nt][0] = ptfa[q][nt][0] + bi30;
                c3[q][nt][1] = ptfa[q][nt][1] + bi30;
                c3[q][nt][2] = ptfa[q][nt][2] + bi31;
                c3[q][nt][3] = ptfa[q][nt][3] + bi31;
                c2[q][nt][0] = ptfa[q][nt][0] + x1lo - bi20;
                c2[q][nt][1] = ptfa[q][nt][1] + x1lo - bi20;
                c2[q][nt][2] = ptfa[q][nt][2] + x1hi - bi21;
                c2[q][nt][3] = ptfa[q][nt][3] + x1hi - bi21;
            }
        }
        #pragma unroll
        for (int ch = 0; ch < 8; ch++) {
            uint4 af3A = ldfrag(OFF_W3,  8, mt0,     ch, lane);
            uint4 af3B = ldfrag(OFF_W3,  8, mt0 + 1, ch, lane);
            uint4 af2A = ldfrag(OFF_W2N, 8, mt0,     ch, lane);
            uint4 af2B = ldfrag(OFF_W2N, 8, mt0 + 1, ch, lane);
            #pragma unroll
            for (int nt = 0; nt < 4; nt++) {
                unsigned bf[2];
                bfrag16(bf, &sm.xn[0][0], XS, nb3 + nt * 8 + g, ch * 16, tig);
                mma_16816_u4(c3[0][nt], af3A, bf);
                mma_16816_u4(c3[1][nt], af3B, bf);
                mma_16816_u4(c2[0][nt], af2A, bf);
                mma_16816_u4(c2[1][nt], af2B, bf);
            }
        }
        #pragma unroll
        for (int q = 0; q < 2; q++) {
            int mb = (mt0 + q) * 16;
            int r0 = mb + g, r1 = mb + g + 8;
            int k0s = K3(r0), k1s = K3(r1);
            #pragma unroll
            for (int nt = 0; nt < 4; nt++) {
                int col0 = nb3 + nt * 8 + 2 * tig;
                int blk = col0 >> 4, w = col0 & 15;
                *reinterpret_cast<__half2*>(&sm.x3[r0][((blk ^ k0s) << 4) + w]) =
                    __floats2half2_rn(c3[q][nt][0], c3[q][nt][1]);
                *reinterpret_cast<__half2*>(&sm.x3[r1][((blk ^ k1s) << 4) + w]) =
                    __floats2half2_rn(c3[q][nt][2], c3[q][nt][3]);
            }
            #pragma unroll
            for (int np = 0; np < 2; np++) {
                int ntE = 2 * np, ntO = 2 * np + 1;
                int pt = (nb3 >> 4) + np;
                uint2 stLo, stHi;
                stLo.x = pack2(c2[q][ntE][0], c2[q][ntE][1]);
                stLo.y = pack2(c2[q][ntO][0], c2[q][ntO][1]);
                stHi.x = pack2(c2[q][ntE][2], c2[q][ntE][3]);
                stHi.y = pack2(c2[q][ntO][2], c2[q][ntO][3]);
                *reinterpret_cast<uint2*>(&sm.xfs[pt][r0 * 16 + 4 * tig]) = stLo;
                *reinterpret_cast<uint2*>(&sm.xfs[pt][r1 * 16 + 4 * tig]) = stHi;
            }
        }
    }
    __syncthreads();

    // ============ Stage 6: h = relu(cw1 @ xfs) — split K across 8 warps ============
    {
        float ca[4] = {0.f, 0.f, 0.f, 0.f}, cbn[4] = {0.f, 0.f, 0.f, 0.f};
        #pragma unroll
        for (int i = 0; i < 8; i++) {
            int ch = warp * 8 + i;
            uint2 u = __ldg(&g_wfrag2[OFF2_CW1 + ch * 32 + lane]);
            uint4 af; af.x = u.x; af.y = 0u; af.z = u.y; af.w = 0u;
            unsigned bf[2];
            bfrag16(bf, &sm.xfs[0][0], XFS, g, ch * 16, tig);
            mma_16816_u4((i & 1) ? cbn : ca, af, bf);
        }
        sm.part[warp][g][2 * tig]     = ca[0] + cbn[0];
        sm.part[warp][g][2 * tig + 1] = ca[1] + cbn[1];
    }
    __syncthreads();
    if (tid < 64) {
        int j = tid & 7, pt = tid >> 3;
        float s = 0.f;
        #pragma unroll
        for (int w = 0; w < 8; w++) s += sm.part[w][j][pt];
        sm.hbufh[pt][j] = __float2half(fmaxf(s, 0.f));
    }
    __syncthreads();

    // ===== Stage 7a: wl = cw2 @ h + cb2 (one mma/warp); softmax over k (shuffles) =====
    {
        int r0 = warp * 16 + g;
        uint2 u = __ldg(&g_wfrag2[OFF2_CW2 + warp * 32 + lane]);
        uint4 af; af.x = u.x; af.y = u.y; af.z = 0u; af.w = 0u;
        unsigned bf[2];
        bf[0] = *reinterpret_cast<const unsigned*>(&sm.hbufh[g][2 * tig]);
        bf[1] = 0u;
        float cb20 = __ldg(&cb2[r0]), cb21 = __ldg(&cb2[r0 + 8]);
        float c[4] = {cb20, cb20, cb21, cb21};
        mma_16816_u4(c, af, bf);
        float m0 = fmaxf(c[0], c[2]), m1 = fmaxf(c[1], c[3]);
        #pragma unroll
        for (int off = 4; off < 32; off <<= 1) {
            m0 = fmaxf(m0, __shfl_xor_sync(0xffffffffu, m0, off));
            m1 = fmaxf(m1, __shfl_xor_sync(0xffffffffu, m1, off));
        }
        float e0 = __expf(c[0] - m0), e2 = __expf(c[2] - m0);
        float e1 = __expf(c[1] - m1), e3 = __expf(c[3] - m1);
        float s0 = e0 + e2, s1 = e1 + e3;
        #pragma unroll
        for (int off = 4; off < 32; off <<= 1) {
            s0 += __shfl_xor_sync(0xffffffffu, s0, off);
            s1 += __shfl_xor_sync(0xffffffffu, s1, off);
        }
        float i0 = 1.f / s0, i1 = 1.f / s1;
        sm.w16[2 * tig][warp][g]         = __float2half(e0 * i0);
        sm.w16[2 * tig][warp][g + 8]     = __float2half(e2 * i0);
        sm.w16[2 * tig + 1][warp][g]     = __float2half(e1 * i1);
        sm.w16[2 * tig + 1][warp][g + 8] = __float2half(e3 * i1);
    }
    __syncthreads();

    // ======== Stage 7b: out_pre = relu(sum_k w16 * x3), conflict-free LDS.128 ========
    {
        int pt = warp;
        #pragma unroll
        for (int q = 0; q < 2; q++) {
            int m = lane + q * 32;
            const uint4* xv = reinterpret_cast<const uint4*>(
                &sm.x3[m][(pt ^ K3(m)) << 4]);
            const uint4* wv = reinterpret_cast<const uint4*>(&sm.w16[pt][m & 7][0]);
            float s = dot_h8(xv[0], wv[0]) + dot_h8(xv[1], wv[1]);
            sm.out_pre[pt][(m & 48) + P16(m & 15)] = __float2half(fmaxf(s, 0.f));
        }
    }
    __syncthreads();

    // ============ Stage 8: out = wout @ out_pre + bout + identity (from xk0) ============
    {
        const int mb = warp * 16;
        int r0 = mb + g, r1 = r0 + 8;
        int p0 = 2 * tig;
        int plo = mb + P16(g);
        float c[4];
        float bo0 = __ldg(&bout[r0]), bo1 = __ldg(&bout[r1]);
        c[0] = bo0 + __half2float(sm.xk0[p0][plo]);
        c[1] = bo0 + __half2float(sm.xk0[p0 + 1][plo]);
        c[2] = bo1 + __half2float(sm.xk0[p0][plo + 2]);
        c[3] = bo1 + __half2float(sm.xk0[p0 + 1][plo + 2]);
        #pragma unroll
        for (int ch = 0; ch < 4; ch++) {
            uint4 af = ldfrag(OFF_WOUT, 4, warp, ch, lane);
            unsigned bf[2];
            bfrag16(bf, &sm.out_pre[0][0], FS, g, ch * 16, tig);
            mma_16816_u4(c, af, bf);
        }
        size_t base = (size_t)b * 128 * NPTS + n0;
        float2 lo, hi;
        lo.x = c[0]; lo.y = c[1];
        hi.x = c[2]; hi.y = c[3];
        *reinterpret_cast<float2*>(&out[base + (size_t)r0 * NPTS + p0]) = lo;
        *reinterpret_cast<float2*>(&out[base + (size_t)r1 * NPTS + p0]) = hi;
    }
}

extern "C" void kernel_launch(void* const* d_in, const int* in_sizes, int n_in,
                              void* d_out, int out_size) {
    (void)in_sizes; (void)n_in; (void)out_size;
    const float* feats = (const float*)d_in[0];
    const float* ppfs  = (const float*)d_in[1];
    const float* w0    = (const float*)d_in[2];
    const float* b0    = (const float*)d_in[3];
    const float* w1    = (const float*)d_in[4];
    const float* b1    = (const float*)d_in[5];
    const float* w2    = (const float*)d_in[6];
    const float* b2    = (const float*)d_in[7];
    const float* w3    = (const float*)d_in[8];
    const float* b3    = (const float*)d_in[9];
    const float* pw1   = (const float*)d_in[10];
    const float* pw2   = (const float*)d_in[11];
    const float* cw1   = (const float*)d_in[12];
    const float* cw2   = (const float*)d_in[13];
    const float* cb2   = (const float*)d_in[14];
    const float* wout  = (const float*)d_in[15];
    const float* bout  = (const float*)d_in[16];
    float* out = (float*)d_out;

    pack_weights_kernel<<<(FRAG_TOTAL + FRAG2_TOTAL + 255) / 256, 256>>>(
        w0, w1, w2, w3, pw1, pw2, cw1, cw2, wout);

    cudaFuncSetAttribute(pt_fused_kernel,
                         cudaFuncAttributeMaxDynamicSharedMemorySize,
                         (int)sizeof(Smem));
    dim3 grid(NPTS / 8, 4, 1);
    pt_fused_kernel<<<grid, 256, sizeof(Smem)>>>(
        feats, ppfs, b0, b1, b2, b3, cb2, bout, out);
}

// round 15
// speedup vs baseline: 1.0832x; 1.0832x over previous
#include <cuda_runtime.h>
#include <cuda_fp16.h>

// ---------------- geometry ----------------
#define NPTS   16384
#define FS     72       // feats/h1/out_pre K-stride (64+8 halves)
#define XS     136      // xn/x3 stride (128+8 halves)
#define XFS    1032     // xfs per-point stride (1024+8 halves)

// ---- pre-packed fp16 A-fragment store (uint4 = af[4] per lane) ----
#define OFF_W0    0        // M=128 K=64   : 8*4*32  = 1024
#define OFF_W1    1024     // M=64  K=128  : 4*8*32  = 1024
#define OFF_W2N   2048     // M=64  K=128  (negated)
#define OFF_W3    3072     // M=64  K=128
#define OFF_PW2   4096     // M=64  K=64   : 4*4*32  = 512
#define OFF_WOUT  4608     // M=128 K=64   : 8*4*32  = 1024
#define FRAG_TOTAL 5632

// ---- half-fragment store (uint2 per lane; other half zeros) ----
#define OFF2_CW1  0        // 64 chunks (M=8, rows 8-15 zero): 64*32 = 2048
#define OFF2_PW1  2048     // 4 chunks  (K=8, k 8-15 zero):    4*32  = 128
#define OFF2_CW2  2176     // 8 chunks  (K=8):                 8*32  = 256
#define FRAG2_TOTAL 2432

__device__ uint4 g_wfrag[FRAG_TOTAL];
__device__ uint2 g_wfrag2[FRAG2_TOTAL];

struct Smem {
    union {
        __half feats[128][FS];     // 18432 B  (stage 0 -> 1)   [4-bit XOR swizzle]
        __half h1[128][FS];        //          (stage 2 -> 3)   [4-bit XOR swizzle]
        __half xfs[8][XFS];        // 16512 B  (stage 4/5 -> 6) [plain]
    } A;
    __half xn[128][XS];            // 34816 B
    __half x3[64][XS];             // 17408 B  [pt-block swizzled by K3(row)]
    __half ppfs[128][8];           // 2048 B
    float  x1[64][8];              // 2048 B
    float  part[8][8][8];          // 2048 B   [warp][j][pt]
    __half hbufh[8][8];            // 128 B    [pt][j]
    __half w16[8][8][24];          // 3072 B   [pt][gg][k]  (gg-stride 48B: bank-safe)
    __half xk0[8][136];            // 2176 B   [pt][P16 pos] k=0 columns of xn
    __half out_pre[8][FS];         // 1152 B   [pt][P16(m)]
};

__device__ __forceinline__ int P16(int i) {
    return 4 * ((i >> 1) & 3) + 2 * (i >> 3) + (i & 1);
}
__device__ __forceinline__ int K3(int r) { return ((r & 7) + (r >> 3)) & 7; }

__device__ __forceinline__ unsigned pack2(float lo, float hi) {
    __half2 h = __floats2half2_rn(lo, hi);
    return *reinterpret_cast<unsigned*>(&h);
}

__device__ __forceinline__ void mma_16816_u4(float* c, uint4 a, const unsigned* b) {
    asm volatile(
        "mma.sync.aligned.m16n8k16.row.col.f32.f16.f16.f32 "
        "{%0,%1,%2,%3}, {%4,%5,%6,%7}, {%8,%9}, {%0,%1,%2,%3};\n"
        : "+f"(c[0]), "+f"(c[1]), "+f"(c[2]), "+f"(c[3])
        : "r"(a.x), "r"(a.y), "r"(a.z), "r"(a.w), "r"(b[0]), "r"(b[1]));
}
__device__ __forceinline__ uint4 ldfrag(int seg, int KC, int m, int ch, int lane) {
    return __ldg(&g_wfrag[seg + (m * KC + ch) * 32 + lane]);
}
// plain B-fragment from a P16-layout smem tile: one 8B load
__device__ __forceinline__ void bfrag16(unsigned bf[2], const __half* T, int S,
                                        int col, int k0, int tig) {
    uint2 v = *reinterpret_cast<const uint2*>(T + col * S + k0 + 4 * tig);
    bf[0] = v.x; bf[1] = v.y;
}
// swizzled B-fragment from region A (FS stride, 4-bit 8B-unit XOR swizzle)
__device__ __forceinline__ void bfragA(unsigned bf[2], const __half* T,
                                       int col, int ch, int tig) {
    int off = col * FS + (((ch * 4 + tig) ^ ((col >> 2) & 15)) << 2);
    uint2 v = *reinterpret_cast<const uint2*>(T + off);
    bf[0] = v.x; bf[1] = v.y;
}
__device__ __forceinline__ uint2 epi_merge(float v0, float v1, float v2, float v3,
                                           int gpar) {
    unsigned ve = pack2(v0, v2);
    unsigned vo = pack2(v1, v3);
    unsigned x  = gpar ? ve : vo;
    unsigned y  = __shfl_xor_sync(0xffffffffu, x, 4);
    unsigned ae = gpar ? y : ve;
    unsigned ao = gpar ? vo : y;
    __half2 he = *reinterpret_cast<__half2*>(&ae);
    __half2 ho = *reinterpret_cast<__half2*>(&ao);
    __half2 lo = __lows2half2(he, ho);
    __half2 hi = __highs2half2(he, ho);
    uint2 st;
    st.x = *reinterpret_cast<unsigned*>(&lo);
    st.y = *reinterpret_cast<unsigned*>(&hi);
    return st;
}
__device__ __forceinline__ float dot_h8(uint4 a, uint4 b) {
    const __half2* A = reinterpret_cast<const __half2*>(&a);
    const __half2* B = reinterpret_cast<const __half2*>(&b);
    float s = 0.f;
    #pragma unroll
    for (int i = 0; i < 4; i++) {
        float2 x = __half22float2(A[i]);
        float2 y = __half22float2(B[i]);
        s += x.x * y.x + x.y * y.y;
    }
    return s;
}

// ============== prep kernel: pack fp32 weights -> fp16 fragments ==============
__global__ void pack_weights_kernel(const float* __restrict__ w0,
                                    const float* __restrict__ w1,
                                    const float* __restrict__ w2,
                                    const float* __restrict__ w3,
                                    const float* __restrict__ pw1,
                                    const float* __restrict__ pw2,
                                    const float* __restrict__ cw1,
                                    const float* __restrict__ cw2,
                                    const float* __restrict__ wout)
{
    int idx = blockIdx.x * blockDim.x + threadIdx.x;
    if (idx >= FRAG_TOTAL + FRAG2_TOTAL) return;

    if (idx < FRAG_TOTAL) {
        const float* W; int Mr, Kr, KC; float sgn = 1.f; int seg;
        if      (idx < OFF_W1)   { seg = OFF_W0;   W = w0;   Mr = 128; Kr = 64;  KC = 4; }
        else if (idx < OFF_W2N)  { seg = OFF_W1;   W = w1;   Mr = 64;  Kr = 128; KC = 8; }
        else if (idx < OFF_W3)   { seg = OFF_W2N;  W = w2;   Mr = 64;  Kr = 128; KC = 8; sgn = -1.f; }
        else if (idx < OFF_PW2)  { seg = OFF_W3;   W = w3;   Mr = 64;  Kr = 128; KC = 8; }
        else if (idx < OFF_WOUT) { seg = OFF_PW2;  W = pw2;  Mr = 64;  Kr = 64;  KC = 4; }
        else                     { seg = OFF_WOUT; W = wout; Mr = 128; Kr = 64;  KC = 4; }

        int li = idx - seg;
        int lane = li & 31;
        int chunk = li >> 5;
        int ch = chunk % KC;
        int m  = chunk / KC;
        int g = lane >> 2, tig = lane & 3;
        int r0 = m * 16 + g;
        int kc = ch * 16 + 2 * tig;
        auto f = [&](int r, int c) -> float {
            return (r < Mr && c < Kr) ? sgn * W[r * Kr + c] : 0.f;
        };
        uint4 v;
        v.x = pack2(f(r0, kc),         f(r0, kc + 1));
        v.y = pack2(f(r0 + 8, kc),     f(r0 + 8, kc + 1));
        v.z = pack2(f(r0, kc + 8),     f(r0, kc + 9));
        v.w = pack2(f(r0 + 8, kc + 8), f(r0 + 8, kc + 9));
        g_wfrag[idx] = v;
    } else {
        int i2 = idx - FRAG_TOTAL;
        int lane = i2 & 31;
        int chunk = i2 >> 5;
        int g = lane >> 2, tig = lane & 3;
        uint2 u;
        if (i2 < OFF2_PW1) {
            // cw1: M=8 (rows 8-15 zero), K=1024; chunk = ch
            int kc = chunk * 16 + 2 * tig;
            u.x = pack2(cw1[g * 1024 + kc],     cw1[g * 1024 + kc + 1]);
            u.y = pack2(cw1[g * 1024 + kc + 8], cw1[g * 1024 + kc + 9]);
        } else if (i2 < OFF2_CW2) {
            // pw1: M=64, K=8 (k 8-15 zero); chunk = m
            int m = (i2 - OFF2_PW1) >> 5;
            int r0 = m * 16 + g;
            int kc = 2 * tig;
            u.x = pack2(pw1[r0 * 8 + kc],       pw1[r0 * 8 + kc + 1]);
            u.y = pack2(pw1[(r0 + 8) * 8 + kc], pw1[(r0 + 8) * 8 + kc + 1]);
        } else {
            // cw2: M=128, K=8; chunk = m (gg)
            int m = (i2 - OFF2_CW2) >> 5;
            int r0 = m * 16 + g;
            int kc = 2 * tig;
            u.x = pack2(cw2[r0 * 8 + kc],       cw2[r0 * 8 + kc + 1]);
            u.y = pack2(cw2[(r0 + 8) * 8 + kc], cw2[(r0 + 8) * 8 + kc + 1]);
        }
        g_wfrag2[i2] = u;
    }
}

// ================================ main kernel ================================
__global__ __launch_bounds__(256, 2)
void pt_fused_kernel(const float* __restrict__ feats, const float* __restrict__ ppfs,
                     const float* __restrict__ b0, const float* __restrict__ b1,
                     const float* __restrict__ b2, const float* __restrict__ b3,
                     const float* __restrict__ cb2, const float* __restrict__ bout,
                     float* __restrict__ out)
{
    extern __shared__ char smraw[];
    Smem& sm = *reinterpret_cast<Smem*>(smraw);

    const int tid  = threadIdx.x;
    const int warp = tid >> 5;
    const int lane = tid & 31;
    const int g    = lane >> 2;
    const int tig  = lane & 3;
    const int b    = blockIdx.y;
    const int n0   = blockIdx.x * 8;

    __half* const Abase = &sm.A.feats[0][0];

    // ============ Stage 0: load feats (P16 quads, 4-bit swizzle) + ppfs ============
    {
        #pragma unroll
        for (int qi = 0; qi < 2; qi++) {
            int q   = warp * 2 + qi;
            int grp = q >> 2;
            int a   = 2 * (q & 3);
            int cb  = grp * 16 + a;
            const float4* pA = reinterpret_cast<const float4*>(
                feats + ((size_t)(b * 64 + cb) * NPTS + n0) * 16);
            const float4* pB = reinterpret_cast<const float4*>(
                feats + ((size_t)(b * 64 + cb + 1) * NPTS + n0) * 16);
            const float4* pC = reinterpret_cast<const float4*>(
                feats + ((size_t)(b * 64 + cb + 8) * NPTS + n0) * 16);
            const float4* pD = reinterpret_cast<const float4*>(
                feats + ((size_t)(b * 64 + cb + 9) * NPTS + n0) * 16);
            float4 vA = __ldg(&pA[lane]);
            float4 vB = __ldg(&pB[lane]);
            float4 vC = __ldg(&pC[lane]);
            float4 vD = __ldg(&pD[lane]);
            int u    = grp * 4 + (a >> 1);
            int xr   = (u ^ (lane & 15)) << 2;
            int colb = lane * 4;
            float fA[4] = {vA.x, vA.y, vA.z, vA.w};
            float fB[4] = {vB.x, vB.y, vB.z, vB.w};
            float fC[4] = {vC.x, vC.y, vC.z, vC.w};
            float fD[4] = {vD.x, vD.y, vD.z, vD.w};
            #pragma unroll
            for (int j = 0; j < 4; j++) {
                uint2 st;
                st.x = pack2(fA[j], fB[j]);
                st.y = pack2(fC[j], fD[j]);
                *reinterpret_cast<uint2*>(Abase + (colb + j) * FS + xr) = st;
            }
        }
        if (warp < 4) {
            int c0 = 2 * warp;
            const float4* p0 = reinterpret_cast<const float4*>(
                ppfs + ((size_t)(b * 8 + c0) * NPTS + n0) * 16);
            const float4* p1 = reinterpret_cast<const float4*>(
                ppfs + ((size_t)(b * 8 + c0 + 1) * NPTS + n0) * 16);
            float4 v0 = __ldg(&p0[lane]);
            float4 v1 = __ldg(&p1[lane]);
            int colb = lane * 4;
            float f0[4] = {v0.x, v0.y, v0.z, v0.w};
            float f1[4] = {v1.x, v1.y, v1.z, v1.w};
            #pragma unroll
            for (int j = 0; j < 4; j++)
                *reinterpret_cast<__half2*>(&sm.ppfs[colb + j][c0]) =
                    __floats2half2_rn(f0[j], f1[j]);
        }
    }
    __syncthreads();

    // ==== Stage 1: xn = relu(w0 @ feats + b0). Warp: 2 m-tiles x 64 cols ====
    {
        const int mt0 = 2 * (warp & 3);
        const int nb  = (warp >> 2) * 64;
        float acc[2][8][4];
        #pragma unroll
        for (int q = 0; q < 2; q++)
            #pragma unroll
            for (int nt = 0; nt < 8; nt++)
                acc[q][nt][0] = acc[q][nt][1] = acc[q][nt][2] = acc[q][nt][3] = 0.f;
        #pragma unroll
        for (int ch = 0; ch < 4; ch++) {
            uint4 afA = ldfrag(OFF_W0, 4, mt0,     ch, lane);
            uint4 afB = ldfrag(OFF_W0, 4, mt0 + 1, ch, lane);
            #pragma unroll
            for (int nt = 0; nt < 8; nt++) {
                unsigned bf[2];
                bfragA(bf, Abase, nb + nt * 8 + g, ch, tig);
                mma_16816_u4(acc[0][nt], afA, bf);
                mma_16816_u4(acc[1][nt], afB, bf);
            }
        }
        #pragma unroll
        for (int q = 0; q < 2; q++) {
            int mb = (mt0 + q) * 16;
            float bi0 = __ldg(&b0[mb + g]), bi1 = __ldg(&b0[mb + g + 8]);
            int pbase = mb + 4 * (g >> 1);
            #pragma unroll
            for (int nt = 0; nt < 8; nt++) {
                float* c = acc[q][nt];
                uint2 st = epi_merge(fmaxf(c[0] + bi0, 0.f), fmaxf(c[1] + bi0, 0.f),
                                     fmaxf(c[2] + bi1, 0.f), fmaxf(c[3] + bi1, 0.f),
                                     g & 1);
                int col = nb + nt * 8 + 2 * tig + (g & 1);
                *reinterpret_cast<uint2*>(&sm.xn[col][pbase]) = st;
                if ((col & 15) == 0)
                    *reinterpret_cast<uint2*>(&sm.xk0[col >> 4][pbase]) = st;
            }
        }
    }
    __syncthreads();

    // ===== Stage 2: warps 0-3: x1 = w1 @ xk0 + b1 ; warps 4-7: h1 = relu(pw1 @ ppfs) =====
    if (warp < 4) {
        const int mb = warp * 16;
        float bi0 = __ldg(&b1[mb + g]), bi1 = __ldg(&b1[mb + g + 8]);
        float acc[4] = {bi0, bi0, bi1, bi1};
        #pragma unroll
        for (int ch = 0; ch < 8; ch++) {
            uint4 af = ldfrag(OFF_W1, 8, warp, ch, lane);
            unsigned bf[2];
            bfrag16(bf, &sm.xk0[0][0], 136, g, ch * 16, tig);
            mma_16816_u4(acc, af, bf);
        }
        sm.x1[mb + g][2 * tig]         = acc[0];
        sm.x1[mb + g][2 * tig + 1]     = acc[1];
        sm.x1[mb + g + 8][2 * tig]     = acc[2];
        sm.x1[mb + g + 8][2 * tig + 1] = acc[3];
    } else {
        const int mb = (warp - 4) * 16;
        uint2 u = __ldg(&g_wfrag2[OFF2_PW1 + (warp - 4) * 32 + lane]);
        uint4 af; af.x = u.x; af.y = u.y; af.z = 0u; af.w = 0u;
        int ub = (mb >> 2) + (g >> 1);
        #pragma unroll
        for (int nt = 0; nt < 16; nt++) {
            unsigned bf[2];
            bf[0] = *reinterpret_cast<const unsigned*>(&sm.ppfs[nt * 8 + g][2 * tig]);
            bf[1] = 0u;
            float c[4] = {0.f, 0.f, 0.f, 0.f};
            mma_16816_u4(c, af, bf);
            uint2 st = epi_merge(fmaxf(c[0], 0.f), fmaxf(c[1], 0.f),
                                 fmaxf(c[2], 0.f), fmaxf(c[3], 0.f), g & 1);
            int col = nt * 8 + 2 * tig + (g & 1);
            int off = col * FS + ((ub ^ ((col >> 2) & 15)) << 2);
            *reinterpret_cast<uint2*>(Abase + off) = st;
        }
    }
    __syncthreads();

    // ==== Stage 3: ptf = pw2 @ h1 (registers). Warp: 2 m-tiles x 32 cols ====
    const int mt0 = 2 * (warp & 1);
    const int nb3 = (warp >> 1) * 32;
    float ptfa[2][4][4];
    {
        #pragma unroll
        for (int q = 0; q < 2; q++)
            #pragma unroll
            for (int nt = 0; nt < 4; nt++)
                ptfa[q][nt][0] = ptfa[q][nt][1] = ptfa[q][nt][2] = ptfa[q][nt][3] = 0.f;
        #pragma unroll
        for (int ch = 0; ch < 4; ch++) {
            uint4 afA = ldfrag(OFF_PW2, 4, mt0,     ch, lane);
            uint4 afB = ldfrag(OFF_PW2, 4, mt0 + 1, ch, lane);
            #pragma unroll
            for (int nt = 0; nt < 4; nt++) {
                unsigned bf[2];
                bfragA(bf, Abase, nb3 + nt * 8 + g, ch, tig);
                mma_16816_u4(ptfa[0][nt], afA, bf);
                mma_16816_u4(ptfa[1][nt], afB, bf);
            }
        }
    }
    __syncthreads();   // h1 dead; xfs (same union) written below

    // ==== Stage 4+5: x3 = w3@xn + b3 + ptf ; xfs = ptf + x1 - (w2@xn + b2) ====
    {
        float c3[2][4][4], c2[2][4][4];
        #pragma unroll
        for (int q = 0; q < 2; q++) {
            int mb = (mt0 + q) * 16;
            float bi30 = __ldg(&b3[mb + g]), bi31 = __ldg(&b3[mb + g + 8]);
            float bi20 = __ldg(&b2[mb + g]), bi21 = __ldg(&b2[mb + g + 8]);
            #pragma unroll
            for (int nt = 0; nt < 4; nt++) {
                int pt = (nb3 >> 4) + (nt >> 1);
                float x1lo = sm.x1[mb + g][pt], x1hi = sm.x1[mb + g + 8][pt];
                c3[q][nt][0] = ptfa[q][nt][0] + bi30;
                c3[q][nt][1] = ptfa[q][nt][1] + bi30;
                c3[q][nt][2] = ptfa[q][nt][2] + bi31;
                c3[q][nt][3] = ptfa[q][nt][3] + bi31;
                c2[q][nt][0] = ptfa[q][nt][0] + x1lo - bi20;
                c2[q][nt][1] = ptfa[q][nt][1] + x1lo - bi20;
                c2[q][nt][2] = ptfa[q][nt][2] + x1hi - bi21;
                c2[q][nt][3] = ptfa[q][nt][3] + x1hi - bi21;
            }
        }
        #pragma unroll
        for (int ch = 0; ch < 8; ch++) {
            uint4 af3A = ldfrag(OFF_W3,  8, mt0,     ch, lane);
            uint4 af3B = ldfrag(OFF_W3,  8, mt0 + 1, ch, lane);
            uint4 af2A = ldfrag(OFF_W2N, 8, mt0,     ch, lane);
            uint4 af2B = ldfrag(OFF_W2N, 8, mt0 + 1, ch, lane);
            #pragma unroll
            for (int nt = 0; nt < 4; nt++) {
                unsigned bf[2];
                bfrag16(bf, &sm.xn[0][0], XS, nb3 + nt * 8 + g, ch * 16, tig);
                mma_16816_u4(c3[0][nt], af3A, bf);
                mma_16816_u4(c3[1][nt], af3B, bf);
                mma_16816_u4(c2[0][nt], af2A, bf);
                mma_16816_u4(c2[1][nt], af2B, bf);
            }
        }
        #pragma unroll
        for (int q = 0; q < 2; q++) {
            int mb = (mt0 + q) * 16;
            int r0 = mb + g, r1 = mb + g + 8;
            int k0s = K3(r0), k1s = K3(r1);
            #pragma unroll
            for (int nt = 0; nt < 4; nt++) {
                int col0 = nb3 + nt * 8 + 2 * tig;
                int blk = col0 >> 4, w = col0 & 15;
                *reinterpret_cast<__half2*>(&sm.x3[r0][((blk ^ k0s) << 4) + w]) =
                    __floats2half2_rn(c3[q][nt][0], c3[q][nt][1]);
                *reinterpret_cast<__half2*>(&sm.x3[r1][((blk ^ k1s) << 4) + w]) =
                    __floats2half2_rn(c3[q][nt][2], c3[q][nt][3]);
            }
            #pragma unroll
            for (int np = 0; np < 2; np++) {
                int ntE = 2 * np, ntO = 2 * np + 1;
                int pt = (nb3 >> 4) + np;
                uint2 stLo, stHi;
                stLo.x = pack2(c2[q][ntE][0], c2[q][ntE][1]);
                stLo.y = pack2(c2[q][ntO][0], c2[q][ntO][1]);
                stHi.x = pack2(c2[q][ntE][2], c2[q][ntE][3]);
                stHi.y = pack2(c2[q][ntO][2], c2[q][ntO][3]);
                *reinterpret_cast<uint2*>(&sm.A.xfs[pt][r0 * 16 + 4 * tig]) = stLo;
                *reinterpret_cast<uint2*>(&sm.A.xfs[pt][r1 * 16 + 4 * tig]) = stHi;
            }
        }
    }
    __syncthreads();

    // ============ Stage 6: h = relu(cw1 @ xfs) — split K across 8 warps ============
    {
        float ca[4] = {0.f, 0.f, 0.f, 0.f}, cbn[4] = {0.f, 0.f, 0.f, 0.f};
        #pragma unroll
        for (int i = 0; i < 8; i++) {
            int ch = warp * 8 + i;
            uint2 u = __ldg(&g_wfrag2[OFF2_CW1 + ch * 32 + lane]);
            uint4 af; af.x = u.x; af.y = 0u; af.z = u.y; af.w = 0u;
            unsigned bf[2];
            bfrag16(bf, &sm.A.xfs[0][0], XFS, g, ch * 16, tig);
            mma_16816_u4((i & 1) ? cbn : ca, af, bf);
        }
        sm.part[warp][g][2 * tig]     = ca[0] + cbn[0];
        sm.part[warp][g][2 * tig + 1] = ca[1] + cbn[1];
    }
    __syncthreads();
    if (tid < 64) {
        int j = tid & 7, pt = tid >> 3;
        float s = 0.f;
        #pragma unroll
        for (int w = 0; w < 8; w++) s += sm.part[w][j][pt];
        sm.hbufh[pt][j] = __float2half(fmaxf(s, 0.f));
    }
    __syncthreads();

    // ===== Stage 7a: wl = cw2 @ h + cb2 (one mma/warp); softmax over k (shuffles) =====
    {
        int r0 = warp * 16 + g;
        uint2 u = __ldg(&g_wfrag2[OFF2_CW2 + warp * 32 + lane]);
        uint4 af; af.x = u.x; af.y = u.y; af.z = 0u; af.w = 0u;
        unsigned bf[2];
        bf[0] = *reinterpret_cast<const unsigned*>(&sm.hbufh[g][2 * tig]);
        bf[1] = 0u;
        float cb20 = __ldg(&cb2[r0]), cb21 = __ldg(&cb2[r0 + 8]);
        float c[4] = {cb20, cb20, cb21, cb21};
        mma_16816_u4(c, af, bf);
        float m0 = fmaxf(c[0], c[2]), m1 = fmaxf(c[1], c[3]);
        #pragma unroll
        for (int off = 4; off < 32; off <<= 1) {
            m0 = fmaxf(m0, __shfl_xor_sync(0xffffffffu, m0, off));
            m1 = fmaxf(m1, __shfl_xor_sync(0xffffffffu, m1, off));
        }
        float e0 = __expf(c[0] - m0), e2 = __expf(c[2] - m0);
        float e1 = __expf(c[1] - m1), e3 = __expf(c[3] - m1);
        float s0 = e0 + e2, s1 = e1 + e3;
        #pragma unroll
        for (int off = 4; off < 32; off <<= 1) {
            s0 += __shfl_xor_sync(0xffffffffu, s0, off);
            s1 += __shfl_xor_sync(0xffffffffu, s1, off);
        }
        float i0 = 1.f / s0, i1 = 1.f / s1;
        sm.w16[2 * tig][warp][g]         = __float2half(e0 * i0);
        sm.w16[2 * tig][warp][g + 8]     = __float2half(e2 * i0);
        sm.w16[2 * tig + 1][warp][g]     = __float2half(e1 * i1);
        sm.w16[2 * tig + 1][warp][g + 8] = __float2half(e3 * i1);
    }
    __syncthreads();

    // ======== Stage 7b: out_pre = relu(sum_k w16 * x3), conflict-free LDS.128 ========
    {
        int pt = warp;
        #pragma unroll
        for (int q = 0; q < 2; q++) {
            int m = lane + q * 32;
            const uint4* xv = reinterpret_cast<const uint4*>(
                &sm.x3[m][(pt ^ K3(m)) << 4]);
            const uint4* wv = reinterpret_cast<const uint4*>(&sm.w16[pt][m & 7][0]);
            float s = dot_h8(xv[0], wv[0]) + dot_h8(xv[1], wv[1]);
            sm.out_pre[pt][(m & 48) + P16(m & 15)] = __float2half(fmaxf(s, 0.f));
        }
    }
    __syncthreads();

    // ============ Stage 8: out = wout @ out_pre + bout + identity (from xk0) ============
    {
        const int mb = warp * 16;
        int r0 = mb + g, r1 = r0 + 8;
        int p0 = 2 * tig;
        int plo = mb + P16(g);
        float c[4];
        float bo0 = __ldg(&bout[r0]), bo1 = __ldg(&bout[r1]);
        c[0] = bo0 + __half2float(sm.xk0[p0][plo]);
        c[1] = bo0 + __half2float(sm.xk0[p0 + 1][plo]);
        c[2] = bo1 + __half2float(sm.xk0[p0][plo + 2]);
        c[3] = bo1 + __half2float(sm.xk0[p0 + 1][plo + 2]);
        #pragma unroll
        for (int ch = 0; ch < 4; ch++) {
            uint4 af = ldfrag(OFF_WOUT, 4, warp, ch, lane);
            unsigned bf[2];
            bfrag16(bf, &sm.out_pre[0][0], FS, g, ch * 16, tig);
            mma_16816_u4(c, af, bf);
        }
        size_t base = (size_t)b * 128 * NPTS + n0;
        float2 lo, hi;
        lo.x = c[0]; lo.y = c[1];
        hi.x = c[2]; hi.y = c[3];
        *reinterpret_cast<float2*>(&out[base + (size_t)r0 * NPTS + p0]) = lo;
        *reinterpret_cast<float2*>(&out[base + (size_t)r1 * NPTS + p0]) = hi;
    }
}

extern "C" void kernel_launch(void* const* d_in, const int* in_sizes, int n_in,
                              void* d_out, int out_size) {
    (void)in_sizes; (void)n_in; (void)out_size;
    const float* feats = (const float*)d_in[0];
    const float* ppfs  = (const float*)d_in[1];
    const float* w0    = (const float*)d_in[2];
    const float* b0    = (const float*)d_in[3];
    const float* w1    = (const float*)d_in[4];
    const float* b1    = (const float*)d_in[5];
    const float* w2    = (const float*)d_in[6];
    const float* b2    = (const float*)d_in[7];
    const float* w3    = (const float*)d_in[8];
    const float* b3    = (const float*)d_in[9];
    const float* pw1   = (const float*)d_in[10];
    const float* pw2   = (const float*)d_in[11];
    const float* cw1   = (const float*)d_in[12];
    const float* cw2   = (const float*)d_in[13];
    const float* cb2   = (const float*)d_in[14];
    const float* wout  = (const float*)d_in[15];
    const float* bout  = (const float*)d_in[16];
    float* out = (float*)d_out;

    pack_weights_kernel<<<(FRAG_TOTAL + FRAG2_TOTAL + 255) / 256, 256>>>(
        w0, w1, w2, w3, pw1, pw2, cw1, cw2, wout);

    cudaFuncSetAttribute(pt_fused_kernel,
                         cudaFuncAttributeMaxDynamicSharedMemorySize,
                         (int)sizeof(Smem));
    dim3 grid(NPTS / 8, 4, 1);
    pt_fused_kernel<<<grid, 256, sizeof(Smem)>>>(
        feats, ppfs, b0, b1, b2, b3, cb2, bout, out);
}